// round 6
// baseline (speedup 1.0000x reference)
#include <cuda_runtime.h>
#include <cstdint>

#define N_NODES 50000
#define N_EDGES 800000

// ---- fused-weight / node-projection scratch (__device__ globals; no alloc) ----
__device__ float g_Wc[96 * 64];        // [k][n]: rows 0..63 = W1[64:128]@W2a, rows 64..95 = W2[64:96]
__device__ float g_AD[64 * 128];       // cols 0..63: A, cols 64..127: D
__device__ float g_bias[64];           // b1@W2a + b2
__device__ float g_PQ[(size_t)N_NODES * 128];  // per-node: P (0..63), Q (64..127)

__device__ __forceinline__ uint32_t f2tf32(float x) {
    uint32_t r;
    asm("cvt.rna.tf32.f32 %0, %1;" : "=r"(r) : "f"(x));
    return r;
}
__device__ __forceinline__ uint32_t smem_u32(const void* p) {
    uint32_t a;
    asm("{ .reg .u64 t; cvta.to.shared.u64 t, %1; cvt.u32.u64 %0, t; }" : "=r"(a) : "l"(p));
    return a;
}
__device__ __forceinline__ void cp16(uint32_t dst, const void* src) {
    asm volatile("cp.async.cg.shared.global [%0], [%1], 16;" :: "r"(dst), "l"(src) : "memory");
}

// ---------------------------------------------------------------------------
// Kernel 1: fuse weights. 48 blocks x 256 thr, one output per thread.
// ---------------------------------------------------------------------------
__global__ void __launch_bounds__(256) prep_kernel(
    const float* __restrict__ W1, const float* __restrict__ b1,
    const float* __restrict__ W2, const float* __restrict__ b2) {
    __shared__ float W2s[64 * 64];
    int t = threadIdx.x;
    for (int i = t; i < 64 * 64; i += 256) W2s[i] = W2[i];
    __syncthreads();

    int o = blockIdx.x * 256 + t;   // 12288 = 192*64 exactly
    {
        int i = o >> 6;
        int j = o & 63;
        float s0 = 0.f, s1 = 0.f, s2 = 0.f, s3 = 0.f;
#pragma unroll
        for (int k = 0; k < 64; k += 4) {
            float4 w = *(const float4*)(W1 + i * 64 + k);
            s0 = fmaf(w.x, W2s[(k + 0) * 64 + j], s0);
            s1 = fmaf(w.y, W2s[(k + 1) * 64 + j], s1);
            s2 = fmaf(w.z, W2s[(k + 2) * 64 + j], s2);
            s3 = fmaf(w.w, W2s[(k + 3) * 64 + j], s3);
        }
        float s = (s0 + s1) + (s2 + s3);
        if (i < 64)       g_AD[i * 128 + j] = s;                 // A
        else if (i < 128) g_Wc[(i - 64) * 64 + j] = s;           // B (e_h block)
        else              g_AD[(i - 128) * 128 + 64 + j] = s;    // D
    }
    if (blockIdx.x == 0) {
        for (int i = t; i < 32 * 64; i += 256) g_Wc[64 * 64 + i] = W2[64 * 64 + i];
        if (t < 64) {
            float s0 = 0.f, s1 = 0.f;
#pragma unroll
            for (int k = 0; k < 64; k += 2) {
                s0 = fmaf(b1[k], W2s[k * 64 + t], s0);
                s1 = fmaf(b1[k + 1], W2s[(k + 1) * 64 + t], s1);
            }
            g_bias[t] = s0 + s1 + b2[t];
        }
    }
}

// ---------------------------------------------------------------------------
// Kernel 2: per-node projections  PQ[n] = [ h[n]@A , h[n]@D ]  (fp32 SIMT)
// ---------------------------------------------------------------------------
__global__ void __launch_bounds__(256) node_kernel(const float* __restrict__ h) {
    __shared__ float ADs[64 * 128];
    __shared__ float Hs[64 * 64];
    int t = threadIdx.x;

    for (int i = t; i < (64 * 128) / 4; i += 256)
        ((float4*)ADs)[i] = ((const float4*)g_AD)[i];

    int n0 = blockIdx.x * 64;
    for (int i = t; i < 1024; i += 256) {
        int m = i >> 4;
        int k4 = (i & 15) << 2;
        int n = n0 + m;
        float4 v = make_float4(0.f, 0.f, 0.f, 0.f);
        if (n < N_NODES) v = *(const float4*)(h + (size_t)n * 64 + k4);
        *(float4*)(Hs + m * 64 + k4) = v;
    }
    __syncthreads();

    int r4 = (t >> 4) << 2;
    int c8 = (t & 15) << 3;

    float acc[4][8];
#pragma unroll
    for (int i = 0; i < 4; i++)
#pragma unroll
        for (int j = 0; j < 8; j++) acc[i][j] = 0.f;

#pragma unroll 2
    for (int k4 = 0; k4 < 64; k4 += 4) {
        float4 a[4];
#pragma unroll
        for (int i = 0; i < 4; i++) a[i] = *(const float4*)(Hs + (r4 + i) * 64 + k4);
        float4 b[4][2];
#pragma unroll
        for (int kk = 0; kk < 4; kk++) {
            b[kk][0] = *(const float4*)(ADs + (k4 + kk) * 128 + c8);
            b[kk][1] = *(const float4*)(ADs + (k4 + kk) * 128 + c8 + 4);
        }
#pragma unroll
        for (int i = 0; i < 4; i++) {
            float av[4] = {a[i].x, a[i].y, a[i].z, a[i].w};
#pragma unroll
            for (int kk = 0; kk < 4; kk++) {
                acc[i][0] = fmaf(av[kk], b[kk][0].x, acc[i][0]);
                acc[i][1] = fmaf(av[kk], b[kk][0].y, acc[i][1]);
                acc[i][2] = fmaf(av[kk], b[kk][0].z, acc[i][2]);
                acc[i][3] = fmaf(av[kk], b[kk][0].w, acc[i][3]);
                acc[i][4] = fmaf(av[kk], b[kk][1].x, acc[i][4]);
                acc[i][5] = fmaf(av[kk], b[kk][1].y, acc[i][5]);
                acc[i][6] = fmaf(av[kk], b[kk][1].z, acc[i][6]);
                acc[i][7] = fmaf(av[kk], b[kk][1].w, acc[i][7]);
            }
        }
    }

#pragma unroll
    for (int i = 0; i < 4; i++) {
        int n = n0 + r4 + i;
        if (n < N_NODES) {
            *(float4*)(g_PQ + (size_t)n * 128 + c8) =
                make_float4(acc[i][0], acc[i][1], acc[i][2], acc[i][3]);
            *(float4*)(g_PQ + (size_t)n * 128 + c8 + 4) =
                make_float4(acc[i][4], acc[i][5], acc[i][6], acc[i][7]);
        }
    }
}

// ---------------------------------------------------------------------------
// Kernel 3: tf32 mma.sync edge GEMM, cp.async double-buffered.
// 512 threads = 16 warps = 4 M-groups x 4 N-groups over a 128x64 tile.
// A staged fp32 via cp.async (2 buffers), cvt->tf32 at frag load. B tf32, once.
// ---------------------------------------------------------------------------
#define TILE_M 128
#define NTILES (N_EDGES / TILE_M)       // 6250
#define EDGE_GRID 148

#define A_STRIDE 100                    // conflict-free frag loads
#define B_STRIDE 72
#define A_WORDS (TILE_M * A_STRIDE)     // 12800
#define SMEM_B_OFF (2 * A_WORDS)        // 25600
#define SMEM_WORDS (SMEM_B_OFF + 96 * B_STRIDE)   // 32512 words = 130048 B

__device__ __forceinline__ void mma_tf32(float c[4], const uint32_t a[4], const uint32_t b[2]) {
    asm volatile(
        "mma.sync.aligned.m16n8k8.row.col.f32.tf32.tf32.f32 "
        "{%0,%1,%2,%3}, {%4,%5,%6,%7}, {%8,%9}, {%0,%1,%2,%3};"
        : "+f"(c[0]), "+f"(c[1]), "+f"(c[2]), "+f"(c[3])
        : "r"(a[0]), "r"(a[1]), "r"(a[2]), "r"(a[3]), "r"(b[0]), "r"(b[1]));
}

__global__ void __launch_bounds__(512, 1) edge_kernel(
    const float* __restrict__ e_h, const float* __restrict__ ext,
    const int* __restrict__ src, const int* __restrict__ dst,
    float* __restrict__ out)
{
    extern __shared__ float smf[];
    uint32_t sbase = smem_u32(smf);
    uint32_t* Bs = (uint32_t*)(smf + SMEM_B_OFF);

    int t = threadIdx.x;
    int wid = t >> 5;
    int lane = t & 31;
    int mw = wid >> 2;        // 0..3 -> rows [mw*32, +32)
    int nw = wid & 3;         // 0..3 -> cols [nw*16, +16)
    int lq = lane >> 2;       // 0..7
    int lr = lane & 3;        // 0..3

    // stage B (weights -> tf32, [k][n] stride 72) — once per CTA
    for (int i = t; i < 96 * 64; i += 512) {
        int k = i >> 6;
        int n = i & 63;
        Bs[k * B_STRIDE + n] = f2tf32(g_Wc[i]);
    }
    // bias regs (2 x float2 per thread)
    float2 bv[2];
#pragma unroll
    for (int nf = 0; nf < 2; nf++)
        bv[nf] = *(const float2*)(g_bias + nw * 16 + nf * 8 + 2 * lr);

    // cp.async staging of one A tile into buffer `buf` (3072 x 16B, 6/thread)
#define STAGE(TL, BUF)                                                          \
    do {                                                                        \
        int _e0 = (TL) * TILE_M;                                                \
        uint32_t _ab = sbase + (BUF) * (A_WORDS * 4);                           \
        _Pragma("unroll")                                                       \
        for (int j = 0; j < 4; j++) {                                           \
            int i = t + j * 512;                                                \
            cp16(_ab + ((i >> 4) * A_STRIDE + ((i & 15) << 2)) * 4,             \
                 e_h + (size_t)(_e0 + (i >> 4)) * 64 + ((i & 15) << 2));        \
        }                                                                       \
        _Pragma("unroll")                                                       \
        for (int j = 0; j < 2; j++) {                                           \
            int i = t + j * 512;                                                \
            cp16(_ab + ((i >> 3) * A_STRIDE + 64 + ((i & 7) << 2)) * 4,         \
                 ext + (size_t)(_e0 + (i >> 3)) * 32 + ((i & 7) << 2));         \
        }                                                                       \
        asm volatile("cp.async.commit_group;" ::: "memory");                    \
    } while (0)

    int tile = blockIdx.x;
    int buf = 0;
    STAGE(tile, 0);
    asm volatile("cp.async.wait_group 0;" ::: "memory");
    __syncthreads();   // A buf0 + Bs + bias visible

    for (; tile < NTILES; tile += EDGE_GRID) {
        int nxt = tile + EDGE_GRID;
        if (nxt < NTILES) STAGE(nxt, buf ^ 1);   // streams during mma + epilogue

        const float* As = smf + buf * A_WORDS;

        // ---- mma mainloop: 12 K-steps of 8 ----
        float c[2][2][4];
#pragma unroll
        for (int mf = 0; mf < 2; mf++)
#pragma unroll
            for (int nf = 0; nf < 2; nf++)
#pragma unroll
                for (int i = 0; i < 4; i++) c[mf][nf][i] = 0.f;

#pragma unroll
        for (int ks = 0; ks < 12; ks++) {
            int kb = ks * 8;
            uint32_t a[2][4];
#pragma unroll
            for (int mf = 0; mf < 2; mf++) {
                const float* ap = As + (mw * 32 + mf * 16 + lq) * A_STRIDE + kb + lr;
                a[mf][0] = f2tf32(ap[0]);
                a[mf][1] = f2tf32(ap[8 * A_STRIDE]);
                a[mf][2] = f2tf32(ap[4]);
                a[mf][3] = f2tf32(ap[8 * A_STRIDE + 4]);
            }
            uint32_t b[2][2];
#pragma unroll
            for (int nf = 0; nf < 2; nf++) {
                const uint32_t* bp = Bs + (kb + lr) * B_STRIDE + nw * 16 + nf * 8 + lq;
                b[nf][0] = bp[0];
                b[nf][1] = bp[4 * B_STRIDE];
            }
#pragma unroll
            for (int mf = 0; mf < 2; mf++)
#pragma unroll
                for (int nf = 0; nf < 2; nf++)
                    mma_tf32(c[mf][nf], a[mf], b[nf]);
        }

        // ---- epilogue: +P[src] +Q[dst] +bias, ReLU, store ----
        int e0 = tile * TILE_M;
#pragma unroll
        for (int mf = 0; mf < 2; mf++) {
#pragma unroll
            for (int half = 0; half < 2; half++) {
                int r = mw * 32 + mf * 16 + half * 8 + lq;
                int e = e0 + r;
                int s = src[e];
                int d = dst[e];
                const float* P = g_PQ + (size_t)s * 128;
                const float* Q = g_PQ + (size_t)d * 128 + 64;
#pragma unroll
                for (int nf = 0; nf < 2; nf++) {
                    int col = nw * 16 + nf * 8 + 2 * lr;
                    float2 p = *(const float2*)(P + col);
                    float2 q = *(const float2*)(Q + col);
                    float cx = c[mf][nf][half * 2 + 0];
                    float cy = c[mf][nf][half * 2 + 1];
                    float2 rv;
                    rv.x = fmaxf(cx + p.x + q.x + bv[nf].x, 0.f);
                    rv.y = fmaxf(cy + p.y + q.y + bv[nf].y, 0.f);
                    *(float2*)(out + (size_t)e * 64 + col) = rv;
                }
            }
        }

        asm volatile("cp.async.wait_group 0;" ::: "memory");
        __syncthreads();   // next buffer complete + all LDS of current done
        buf ^= 1;
    }
#undef STAGE
}

// ---------------------------------------------------------------------------
extern "C" void kernel_launch(void* const* d_in, const int* in_sizes, int n_in,
                              void* d_out, int out_size) {
    const float* h   = (const float*)d_in[0];
    const float* e_h = (const float*)d_in[1];
    const float* ext = (const float*)d_in[2];
    const float* W1  = (const float*)d_in[3];
    const float* b1  = (const float*)d_in[4];
    const float* W2  = (const float*)d_in[5];
    const float* b2  = (const float*)d_in[6];
    const int*   src = (const int*)d_in[7];
    const int*   dst = (const int*)d_in[8];
    float* out = (float*)d_out;

    static bool attr_set = false;
    if (!attr_set) {
        cudaFuncSetAttribute(edge_kernel, cudaFuncAttributeMaxDynamicSharedMemorySize,
                             SMEM_WORDS * 4);
        attr_set = true;
    }

    prep_kernel<<<48, 256>>>(W1, b1, W2, b2);
    node_kernel<<<(N_NODES + 63) / 64, 256>>>(h);
    edge_kernel<<<EDGE_GRID, 512, SMEM_WORDS * 4>>>(e_h, ext, src, dst, out);
}

// round 7
// speedup vs baseline: 1.1412x; 1.1412x over previous
#include <cuda_runtime.h>
#include <cstdint>

#define N_NODES 50000
#define N_EDGES 800000

// ---- fused-weight / node-projection scratch (__device__ globals; no alloc) ----
__device__ float g_Wc[96 * 64];        // [k][n]: rows 0..63 = W1[64:128]@W2a, rows 64..95 = W2[64:96]
__device__ float g_AD[64 * 128];       // cols 0..63: A, cols 64..127: D
__device__ float g_bias[64];           // b1@W2a + b2
__device__ float g_PQ[(size_t)N_NODES * 128];  // per-node: P (0..63), Q (64..127)

__device__ __forceinline__ uint32_t f2tf32(float x) {
    uint32_t r;
    asm("cvt.rna.tf32.f32 %0, %1;" : "=r"(r) : "f"(x));
    return r;
}
__device__ __forceinline__ uint32_t smem_u32(const void* p) {
    uint32_t a;
    asm("{ .reg .u64 t; cvta.to.shared.u64 t, %1; cvt.u32.u64 %0, t; }" : "=r"(a) : "l"(p));
    return a;
}
__device__ __forceinline__ void cp16(uint32_t dst, const void* src) {
    asm volatile("cp.async.cg.shared.global [%0], [%1], 16;" :: "r"(dst), "l"(src) : "memory");
}

// ---------------------------------------------------------------------------
// Kernel 1: fuse weights. 48 blocks x 256 thr, one output per thread.
// ---------------------------------------------------------------------------
__global__ void __launch_bounds__(256) prep_kernel(
    const float* __restrict__ W1, const float* __restrict__ b1,
    const float* __restrict__ W2, const float* __restrict__ b2) {
    __shared__ float W2s[64 * 64];
    int t = threadIdx.x;
    for (int i = t; i < 64 * 64; i += 256) W2s[i] = W2[i];
    __syncthreads();

    int o = blockIdx.x * 256 + t;   // 12288 = 192*64 exactly
    {
        int i = o >> 6;
        int j = o & 63;
        float s0 = 0.f, s1 = 0.f, s2 = 0.f, s3 = 0.f;
#pragma unroll
        for (int k = 0; k < 64; k += 4) {
            float4 w = *(const float4*)(W1 + i * 64 + k);
            s0 = fmaf(w.x, W2s[(k + 0) * 64 + j], s0);
            s1 = fmaf(w.y, W2s[(k + 1) * 64 + j], s1);
            s2 = fmaf(w.z, W2s[(k + 2) * 64 + j], s2);
            s3 = fmaf(w.w, W2s[(k + 3) * 64 + j], s3);
        }
        float s = (s0 + s1) + (s2 + s3);
        if (i < 64)       g_AD[i * 128 + j] = s;                 // A
        else if (i < 128) g_Wc[(i - 64) * 64 + j] = s;           // B (e_h block)
        else              g_AD[(i - 128) * 128 + 64 + j] = s;    // D
    }
    if (blockIdx.x == 0) {
        for (int i = t; i < 32 * 64; i += 256) g_Wc[64 * 64 + i] = W2[64 * 64 + i];
        if (t < 64) {
            float s0 = 0.f, s1 = 0.f;
#pragma unroll
            for (int k = 0; k < 64; k += 2) {
                s0 = fmaf(b1[k], W2s[k * 64 + t], s0);
                s1 = fmaf(b1[k + 1], W2s[(k + 1) * 64 + t], s1);
            }
            g_bias[t] = s0 + s1 + b2[t];
        }
    }
}

// ---------------------------------------------------------------------------
// Kernel 2: per-node projections  PQ[n] = [ h[n]@A , h[n]@D ]  (fp32 SIMT)
// ---------------------------------------------------------------------------
__global__ void __launch_bounds__(256) node_kernel(const float* __restrict__ h) {
    __shared__ float ADs[64 * 128];
    __shared__ float Hs[64 * 64];
    int t = threadIdx.x;

    for (int i = t; i < (64 * 128) / 4; i += 256)
        ((float4*)ADs)[i] = ((const float4*)g_AD)[i];

    int n0 = blockIdx.x * 64;
    for (int i = t; i < 1024; i += 256) {
        int m = i >> 4;
        int k4 = (i & 15) << 2;
        int n = n0 + m;
        float4 v = make_float4(0.f, 0.f, 0.f, 0.f);
        if (n < N_NODES) v = *(const float4*)(h + (size_t)n * 64 + k4);
        *(float4*)(Hs + m * 64 + k4) = v;
    }
    __syncthreads();

    int r4 = (t >> 4) << 2;
    int c8 = (t & 15) << 3;

    float acc[4][8];
#pragma unroll
    for (int i = 0; i < 4; i++)
#pragma unroll
        for (int j = 0; j < 8; j++) acc[i][j] = 0.f;

#pragma unroll 2
    for (int k4 = 0; k4 < 64; k4 += 4) {
        float4 a[4];
#pragma unroll
        for (int i = 0; i < 4; i++) a[i] = *(const float4*)(Hs + (r4 + i) * 64 + k4);
        float4 b[4][2];
#pragma unroll
        for (int kk = 0; kk < 4; kk++) {
            b[kk][0] = *(const float4*)(ADs + (k4 + kk) * 128 + c8);
            b[kk][1] = *(const float4*)(ADs + (k4 + kk) * 128 + c8 + 4);
        }
#pragma unroll
        for (int i = 0; i < 4; i++) {
            float av[4] = {a[i].x, a[i].y, a[i].z, a[i].w};
#pragma unroll
            for (int kk = 0; kk < 4; kk++) {
                acc[i][0] = fmaf(av[kk], b[kk][0].x, acc[i][0]);
                acc[i][1] = fmaf(av[kk], b[kk][0].y, acc[i][1]);
                acc[i][2] = fmaf(av[kk], b[kk][0].z, acc[i][2]);
                acc[i][3] = fmaf(av[kk], b[kk][0].w, acc[i][3]);
                acc[i][4] = fmaf(av[kk], b[kk][1].x, acc[i][4]);
                acc[i][5] = fmaf(av[kk], b[kk][1].y, acc[i][5]);
                acc[i][6] = fmaf(av[kk], b[kk][1].z, acc[i][6]);
                acc[i][7] = fmaf(av[kk], b[kk][1].w, acc[i][7]);
            }
        }
    }

#pragma unroll
    for (int i = 0; i < 4; i++) {
        int n = n0 + r4 + i;
        if (n < N_NODES) {
            *(float4*)(g_PQ + (size_t)n * 128 + c8) =
                make_float4(acc[i][0], acc[i][1], acc[i][2], acc[i][3]);
            *(float4*)(g_PQ + (size_t)n * 128 + c8 + 4) =
                make_float4(acc[i][4], acc[i][5], acc[i][6], acc[i][7]);
        }
    }
}

// ---------------------------------------------------------------------------
// Kernel 3: tf32 mma.sync edge GEMM, cp.async double-buffered, 64-edge tiles.
// 256 threads = 8 warps = 4 M-groups (16 rows) x 2 N-groups (32 cols).
// 2 CTAs/SM (the R4 overlap mechanism) + intra-CTA cp.async pipeline.
// ---------------------------------------------------------------------------
#define TILE_M 64
#define NTILES (N_EDGES / TILE_M)       // 12500
#define EDGE_GRID 296                   // 148 SMs x 2 CTAs

#define A_STRIDE 100                    // conflict-free frag loads (bank = 4*lq + lr)
#define B_STRIDE 72                     // conflict-free (bank = 8*lr + lq + 8*nf)
#define A_WORDS (TILE_M * A_STRIDE)     // 6400
#define SMEM_B_OFF (2 * A_WORDS)        // 12800
#define SMEM_WORDS (SMEM_B_OFF + 96 * B_STRIDE)   // 19712 words = 78848 B

__device__ __forceinline__ void mma_tf32(float c[4], const uint32_t a[4], const uint32_t b[2]) {
    asm volatile(
        "mma.sync.aligned.m16n8k8.row.col.f32.tf32.tf32.f32 "
        "{%0,%1,%2,%3}, {%4,%5,%6,%7}, {%8,%9}, {%0,%1,%2,%3};"
        : "+f"(c[0]), "+f"(c[1]), "+f"(c[2]), "+f"(c[3])
        : "r"(a[0]), "r"(a[1]), "r"(a[2]), "r"(a[3]), "r"(b[0]), "r"(b[1]));
}

__global__ void __launch_bounds__(256, 2) edge_kernel(
    const float* __restrict__ e_h, const float* __restrict__ ext,
    const int* __restrict__ src, const int* __restrict__ dst,
    float* __restrict__ out)
{
    extern __shared__ float smf[];
    uint32_t sbase = smem_u32(smf);
    uint32_t* Bs = (uint32_t*)(smf + SMEM_B_OFF);

    int t = threadIdx.x;
    int wid = t >> 5;
    int lane = t & 31;
    int mw = wid & 3;         // 0..3 -> rows [mw*16, +16)
    int nw = wid >> 2;        // 0..1 -> cols [nw*32, +32)
    int lq = lane >> 2;       // 0..7
    int lr = lane & 3;        // 0..3

    // stage B (weights -> tf32, [k][n] stride 72) — once per CTA
    for (int i = t; i < 96 * 64; i += 256) {
        int k = i >> 6;
        int n = i & 63;
        Bs[k * B_STRIDE + n] = f2tf32(g_Wc[i]);
    }
    // bias regs (4 x float2 per thread)
    float2 bv[4];
#pragma unroll
    for (int nf = 0; nf < 4; nf++)
        bv[nf] = *(const float2*)(g_bias + nw * 32 + nf * 8 + 2 * lr);

    // cp.async staging of one 64-edge A tile (fp32) into buffer BUF (6/thread)
#define STAGE(TL, BUF)                                                          \
    do {                                                                        \
        int _e0 = (TL) * TILE_M;                                                \
        uint32_t _ab = sbase + (BUF) * (A_WORDS * 4);                           \
        _Pragma("unroll")                                                       \
        for (int j = 0; j < 4; j++) {                                           \
            int i = t + j * 256;                                                \
            cp16(_ab + ((i >> 4) * A_STRIDE + ((i & 15) << 2)) * 4,             \
                 e_h + (size_t)(_e0 + (i >> 4)) * 64 + ((i & 15) << 2));        \
        }                                                                       \
        _Pragma("unroll")                                                       \
        for (int j = 0; j < 2; j++) {                                           \
            int i = t + j * 256;                                                \
            cp16(_ab + ((i >> 3) * A_STRIDE + 64 + ((i & 7) << 2)) * 4,         \
                 ext + (size_t)(_e0 + (i >> 3)) * 32 + ((i & 7) << 2));         \
        }                                                                       \
        asm volatile("cp.async.commit_group;" ::: "memory");                    \
    } while (0)

    int tile = blockIdx.x;
    int buf = 0;
    STAGE(tile, 0);
    asm volatile("cp.async.wait_group 0;" ::: "memory");
    __syncthreads();   // A buf0 + Bs visible

    for (; tile < NTILES; tile += EDGE_GRID) {
        int nxt = tile + EDGE_GRID;
        if (nxt < NTILES) STAGE(nxt, buf ^ 1);   // streams during mma + epilogue

        const float* As = smf + buf * A_WORDS;
        int e0 = tile * TILE_M;

        // prefetch gather indices for this thread's 2 edge rows
        int er0 = e0 + mw * 16 + lq;
        int er1 = er0 + 8;
        int s0 = src[er0], d0 = dst[er0];
        int s1 = src[er1], d1 = dst[er1];

        // ---- mma mainloop: 12 K-steps of 8 ----
        float c[4][4];
#pragma unroll
        for (int nf = 0; nf < 4; nf++)
#pragma unroll
            for (int i = 0; i < 4; i++) c[nf][i] = 0.f;

#pragma unroll
        for (int ks = 0; ks < 12; ks++) {
            int kb = ks * 8;
            uint32_t a[4];
            {
                const float* ap = As + (mw * 16 + lq) * A_STRIDE + kb + lr;
                a[0] = f2tf32(ap[0]);
                a[1] = f2tf32(ap[8 * A_STRIDE]);
                a[2] = f2tf32(ap[4]);
                a[3] = f2tf32(ap[8 * A_STRIDE + 4]);
            }
            uint32_t b[4][2];
#pragma unroll
            for (int nf = 0; nf < 4; nf++) {
                const uint32_t* bp = Bs + (kb + lr) * B_STRIDE + nw * 32 + nf * 8 + lq;
                b[nf][0] = bp[0];
                b[nf][1] = bp[4 * B_STRIDE];
            }
#pragma unroll
            for (int nf = 0; nf < 4; nf++)
                mma_tf32(c[nf], a, b[nf]);
        }

        // ---- epilogue: +P[src] +Q[dst] +bias, ReLU, store ----
#pragma unroll
        for (int half = 0; half < 2; half++) {
            int e = half ? er1 : er0;
            int s = half ? s1 : s0;
            int d = half ? d1 : d0;
            const float* P = g_PQ + (size_t)s * 128;
            const float* Q = g_PQ + (size_t)d * 128 + 64;
#pragma unroll
            for (int nf = 0; nf < 4; nf++) {
                int col = nw * 32 + nf * 8 + 2 * lr;
                float2 p = *(const float2*)(P + col);
                float2 q = *(const float2*)(Q + col);
                float cx = c[nf][half * 2 + 0];
                float cy = c[nf][half * 2 + 1];
                float2 rv;
                rv.x = fmaxf(cx + p.x + q.x + bv[nf].x, 0.f);
                rv.y = fmaxf(cy + p.y + q.y + bv[nf].y, 0.f);
                *(float2*)(out + (size_t)e * 64 + col) = rv;
            }
        }

        asm volatile("cp.async.wait_group 0;" ::: "memory");
        __syncthreads();   // next buffer complete + all LDS of current done
        buf ^= 1;
    }
#undef STAGE
}

// ---------------------------------------------------------------------------
extern "C" void kernel_launch(void* const* d_in, const int* in_sizes, int n_in,
                              void* d_out, int out_size) {
    const float* h   = (const float*)d_in[0];
    const float* e_h = (const float*)d_in[1];
    const float* ext = (const float*)d_in[2];
    const float* W1  = (const float*)d_in[3];
    const float* b1  = (const float*)d_in[4];
    const float* W2  = (const float*)d_in[5];
    const float* b2  = (const float*)d_in[6];
    const int*   src = (const int*)d_in[7];
    const int*   dst = (const int*)d_in[8];
    float* out = (float*)d_out;

    static bool attr_set = false;
    if (!attr_set) {
        cudaFuncSetAttribute(edge_kernel, cudaFuncAttributeMaxDynamicSharedMemorySize,
                             SMEM_WORDS * 4);
        attr_set = true;
    }

    prep_kernel<<<48, 256>>>(W1, b1, W2, b2);
    node_kernel<<<(N_NODES + 63) / 64, 256>>>(h);
    edge_kernel<<<EDGE_GRID, 256, SMEM_WORDS * 4>>>(e_h, ext, src, dst, out);
}

// round 9
// speedup vs baseline: 1.3978x; 1.2249x over previous
#include <cuda_runtime.h>
#include <cstdint>

#define N_NODES 50000
#define N_EDGES 800000

// ---- fused-weight / node-projection scratch (__device__ globals; no alloc) ----
__device__ float g_Wc[96 * 64];        // [k][n]: rows 0..63 = W1[64:128]@W2a, rows 64..95 = W2[64:96]
__device__ float g_AD[64 * 128];       // cols 0..63: A, cols 64..127: D
__device__ float g_bias[64];           // b1@W2a + b2
__device__ float g_PQ[(size_t)N_NODES * 128];  // per-node: P (0..63), Q (64..127)

__device__ __forceinline__ uint32_t f2tf32(float x) {
    uint32_t r;
    asm("cvt.rna.tf32.f32 %0, %1;" : "=r"(r) : "f"(x));
    return r;
}
// streaming store (evict-first)
__device__ __forceinline__ void stg_cs(float* p, float2 v) {
    asm volatile("st.global.cs.v2.f32 [%0], {%1,%2};" :: "l"(p), "f"(v.x), "f"(v.y));
}

// ---------------------------------------------------------------------------
// Kernel 1: fuse weights. 48 blocks x 256 thr, one output per thread.
// ---------------------------------------------------------------------------
__global__ void __launch_bounds__(256) prep_kernel(
    const float* __restrict__ W1, const float* __restrict__ b1,
    const float* __restrict__ W2, const float* __restrict__ b2) {
    __shared__ float W2s[64 * 64];
    int t = threadIdx.x;
    for (int i = t; i < 64 * 64; i += 256) W2s[i] = W2[i];
    __syncthreads();

    int o = blockIdx.x * 256 + t;   // 12288 = 192*64 exactly
    {
        int i = o >> 6;
        int j = o & 63;
        float s0 = 0.f, s1 = 0.f, s2 = 0.f, s3 = 0.f;
#pragma unroll
        for (int k = 0; k < 64; k += 4) {
            float4 w = *(const float4*)(W1 + i * 64 + k);
            s0 = fmaf(w.x, W2s[(k + 0) * 64 + j], s0);
            s1 = fmaf(w.y, W2s[(k + 1) * 64 + j], s1);
            s2 = fmaf(w.z, W2s[(k + 2) * 64 + j], s2);
            s3 = fmaf(w.w, W2s[(k + 3) * 64 + j], s3);
        }
        float s = (s0 + s1) + (s2 + s3);
        if (i < 64)       g_AD[i * 128 + j] = s;                 // A
        else if (i < 128) g_Wc[(i - 64) * 64 + j] = s;           // B (e_h block)
        else              g_AD[(i - 128) * 128 + 64 + j] = s;    // D
    }
    if (blockIdx.x == 0) {
        for (int i = t; i < 32 * 64; i += 256) g_Wc[64 * 64 + i] = W2[64 * 64 + i];
        if (t < 64) {
            float s0 = 0.f, s1 = 0.f;
#pragma unroll
            for (int k = 0; k < 64; k += 2) {
                s0 = fmaf(b1[k], W2s[k * 64 + t], s0);
                s1 = fmaf(b1[k + 1], W2s[(k + 1) * 64 + t], s1);
            }
            g_bias[t] = s0 + s1 + b2[t];
        }
    }
}

// ---------------------------------------------------------------------------
// Kernel 2: per-node projections  PQ[n] = [ h[n]@A , h[n]@D ]  (fp32 SIMT)
// ---------------------------------------------------------------------------
__global__ void __launch_bounds__(256) node_kernel(const float* __restrict__ h) {
    __shared__ float ADs[64 * 128];
    __shared__ float Hs[64 * 64];
    int t = threadIdx.x;

    for (int i = t; i < (64 * 128) / 4; i += 256)
        ((float4*)ADs)[i] = ((const float4*)g_AD)[i];

    int n0 = blockIdx.x * 64;
    for (int i = t; i < 1024; i += 256) {
        int m = i >> 4;
        int k4 = (i & 15) << 2;
        int n = n0 + m;
        float4 v = make_float4(0.f, 0.f, 0.f, 0.f);
        if (n < N_NODES) v = *(const float4*)(h + (size_t)n * 64 + k4);
        *(float4*)(Hs + m * 64 + k4) = v;
    }
    __syncthreads();

    int r4 = (t >> 4) << 2;
    int c8 = (t & 15) << 3;

    float acc[4][8];
#pragma unroll
    for (int i = 0; i < 4; i++)
#pragma unroll
        for (int j = 0; j < 8; j++) acc[i][j] = 0.f;

#pragma unroll 2
    for (int k4 = 0; k4 < 64; k4 += 4) {
        float4 a[4];
#pragma unroll
        for (int i = 0; i < 4; i++) a[i] = *(const float4*)(Hs + (r4 + i) * 64 + k4);
        float4 b[4][2];
#pragma unroll
        for (int kk = 0; kk < 4; kk++) {
            b[kk][0] = *(const float4*)(ADs + (k4 + kk) * 128 + c8);
            b[kk][1] = *(const float4*)(ADs + (k4 + kk) * 128 + c8 + 4);
        }
#pragma unroll
        for (int i = 0; i < 4; i++) {
            float av[4] = {a[i].x, a[i].y, a[i].z, a[i].w};
#pragma unroll
            for (int kk = 0; kk < 4; kk++) {
                acc[i][0] = fmaf(av[kk], b[kk][0].x, acc[i][0]);
                acc[i][1] = fmaf(av[kk], b[kk][0].y, acc[i][1]);
                acc[i][2] = fmaf(av[kk], b[kk][0].z, acc[i][2]);
                acc[i][3] = fmaf(av[kk], b[kk][0].w, acc[i][3]);
                acc[i][4] = fmaf(av[kk], b[kk][1].x, acc[i][4]);
                acc[i][5] = fmaf(av[kk], b[kk][1].y, acc[i][5]);
                acc[i][6] = fmaf(av[kk], b[kk][1].z, acc[i][6]);
                acc[i][7] = fmaf(av[kk], b[kk][1].w, acc[i][7]);
            }
        }
    }

#pragma unroll
    for (int i = 0; i < 4; i++) {
        int n = n0 + r4 + i;
        if (n < N_NODES) {
            *(float4*)(g_PQ + (size_t)n * 128 + c8) =
                make_float4(acc[i][0], acc[i][1], acc[i][2], acc[i][3]);
            *(float4*)(g_PQ + (size_t)n * 128 + c8 + 4) =
                make_float4(acc[i][4], acc[i][5], acc[i][6], acc[i][7]);
        }
    }
}

// ---------------------------------------------------------------------------
// Kernel 3: tf32 mma.sync edge GEMM (exact R4 structure) + cache-policy fixes:
// streams evict-first (__ldcs / st.cs), PQ gathers default (protected by the
// streams not competing for L2), indices prefetched pre-mainloop.
// ---------------------------------------------------------------------------
#define TILE_M 128
#define NTILES (N_EDGES / TILE_M)       // 6250
#define EDGE_GRID 296                   // 148 SMs x 2 CTAs

#define A_STRIDE 100                    // conflict-free frag loads
#define B_STRIDE 72
#define SMEM_A_OFF 0
#define SMEM_B_OFF (TILE_M * A_STRIDE)             // 12800 words
#define SMEM_BIAS_OFF (SMEM_B_OFF + 96 * B_STRIDE) // 19712 words
#define SMEM_WORDS (SMEM_BIAS_OFF + 64)            // 19776 words = 79104 B

__device__ __forceinline__ void mma_tf32(float c[4], const uint32_t a[4], const uint32_t b[2]) {
    asm volatile(
        "mma.sync.aligned.m16n8k8.row.col.f32.tf32.tf32.f32 "
        "{%0,%1,%2,%3}, {%4,%5,%6,%7}, {%8,%9}, {%0,%1,%2,%3};"
        : "+f"(c[0]), "+f"(c[1]), "+f"(c[2]), "+f"(c[3])
        : "r"(a[0]), "r"(a[1]), "r"(a[2]), "r"(a[3]), "r"(b[0]), "r"(b[1]));
}

__global__ void __launch_bounds__(256, 2) edge_kernel(
    const float* __restrict__ e_h, const float* __restrict__ ext,
    const int* __restrict__ src, const int* __restrict__ dst,
    float* __restrict__ out)
{
    extern __shared__ uint32_t smw[];
    uint32_t* As = smw + SMEM_A_OFF;
    uint32_t* Bs = smw + SMEM_B_OFF;
    float*  bias = (float*)(smw + SMEM_BIAS_OFF);

    int t = threadIdx.x;
    int wid = t >> 5;
    int lane = t & 31;
    int mw = wid >> 1;        // 0..3 -> M rows [mw*32, +32)
    int nw = wid & 1;         // 0..1 -> N cols [nw*32, +32)
    int lq = lane >> 2;       // 0..7
    int lr = lane & 3;        // 0..3

    // stage B (weights, tf32, [k][n] stride 72) + bias — once per CTA
    for (int i = t; i < 96 * 64; i += 256) {
        int k = i >> 6;
        int n = i & 63;
        Bs[k * B_STRIDE + n] = f2tf32(g_Wc[i]);
    }
    if (t < 64) bias[t] = g_bias[t];

    for (int tile = blockIdx.x; tile < NTILES; tile += EDGE_GRID) {
        int e0 = tile * TILE_M;
        __syncthreads();   // prev-iter LDS of As done (first iter: B/bias visible)

        // ---- stage A: e_h -> cols 0..63 (streaming load, cvt to tf32) ----
#pragma unroll
        for (int i = t; i < 2048; i += 256) {
            int m = i >> 4;
            int c4 = (i & 15) << 2;
            float4 v = __ldcs((const float4*)(e_h + (size_t)(e0 + m) * 64 + c4));
            uint4 w = make_uint4(f2tf32(v.x), f2tf32(v.y), f2tf32(v.z), f2tf32(v.w));
            *(uint4*)(As + m * A_STRIDE + c4) = w;
        }
        // ---- stage A: ext -> cols 64..95 ----
#pragma unroll
        for (int i = t; i < 1024; i += 256) {
            int m = i >> 3;
            int c4 = (i & 7) << 2;
            float4 v = __ldcs((const float4*)(ext + (size_t)(e0 + m) * 32 + c4));
            uint4 w = make_uint4(f2tf32(v.x), f2tf32(v.y), f2tf32(v.z), f2tf32(v.w));
            *(uint4*)(As + m * A_STRIDE + 64 + c4) = w;
        }

        // ---- prefetch gather indices for this thread's 4 edge rows ----
        int sv[2][2], dv[2][2];
#pragma unroll
        for (int mf = 0; mf < 2; mf++)
#pragma unroll
            for (int half = 0; half < 2; half++) {
                int e = e0 + mw * 32 + mf * 16 + half * 8 + lq;
                sv[mf][half] = src[e];
                dv[mf][half] = dst[e];
            }
        __syncthreads();

        // ---- mma mainloop: 12 K-steps of 8 ----
        float c[2][4][4];
#pragma unroll
        for (int mf = 0; mf < 2; mf++)
#pragma unroll
            for (int nf = 0; nf < 4; nf++)
#pragma unroll
                for (int i = 0; i < 4; i++) c[mf][nf][i] = 0.f;

#pragma unroll
        for (int ks = 0; ks < 12; ks++) {
            int kb = ks * 8;
            uint32_t a[2][4];
#pragma unroll
            for (int mf = 0; mf < 2; mf++) {
                const uint32_t* ap = As + (mw * 32 + mf * 16 + lq) * A_STRIDE + kb + lr;
                a[mf][0] = ap[0];
                a[mf][1] = ap[8 * A_STRIDE];
                a[mf][2] = ap[4];
                a[mf][3] = ap[8 * A_STRIDE + 4];
            }
            uint32_t b[4][2];
#pragma unroll
            for (int nf = 0; nf < 4; nf++) {
                const uint32_t* bp = Bs + (kb + lr) * B_STRIDE + nw * 32 + nf * 8 + lq;
                b[nf][0] = bp[0];
                b[nf][1] = bp[4 * B_STRIDE];
            }
#pragma unroll
            for (int mf = 0; mf < 2; mf++)
#pragma unroll
                for (int nf = 0; nf < 4; nf++)
                    mma_tf32(c[mf][nf], a[mf], b[nf]);
        }

        // ---- epilogue: +P[src] +Q[dst] +bias, ReLU, streaming store ----
#pragma unroll
        for (int mf = 0; mf < 2; mf++) {
#pragma unroll
            for (int half = 0; half < 2; half++) {
                int r = mw * 32 + mf * 16 + half * 8 + lq;
                int e = e0 + r;
                const float* P = g_PQ + (size_t)sv[mf][half] * 128;
                const float* Q = g_PQ + (size_t)dv[mf][half] * 128 + 64;
#pragma unroll
                for (int nf = 0; nf < 4; nf++) {
                    int col = nw * 32 + nf * 8 + 2 * lr;
                    float2 p = __ldg((const float2*)(P + col));
                    float2 q = __ldg((const float2*)(Q + col));
                    float2 bvv = *(const float2*)(bias + col);
                    float cx = c[mf][nf][half * 2 + 0];
                    float cy = c[mf][nf][half * 2 + 1];
                    float2 rv;
                    rv.x = fmaxf(cx + p.x + q.x + bvv.x, 0.f);
                    rv.y = fmaxf(cy + p.y + q.y + bvv.y, 0.f);
                    stg_cs(out + (size_t)e * 64 + col, rv);
                }
            }
        }
    }
}

// ---------------------------------------------------------------------------
extern "C" void kernel_launch(void* const* d_in, const int* in_sizes, int n_in,
                              void* d_out, int out_size) {
    const float* h   = (const float*)d_in[0];
    const float* e_h = (const float*)d_in[1];
    const float* ext = (const float*)d_in[2];
    const float* W1  = (const float*)d_in[3];
    const float* b1  = (const float*)d_in[4];
    const float* W2  = (const float*)d_in[5];
    const float* b2  = (const float*)d_in[6];
    const int*   src = (const int*)d_in[7];
    const int*   dst = (const int*)d_in[8];
    float* out = (float*)d_out;

    static bool attr_set = false;
    if (!attr_set) {
        cudaFuncSetAttribute(edge_kernel, cudaFuncAttributeMaxDynamicSharedMemorySize,
                             SMEM_WORDS * 4);
        attr_set = true;
    }

    prep_kernel<<<48, 256>>>(W1, b1, W2, b2);
    node_kernel<<<(N_NODES + 63) / 64, 256>>>(h);
    edge_kernel<<<EDGE_GRID, 256, SMEM_WORDS * 4>>>(e_h, ext, src, dst, out);
}